// round 1
// baseline (speedup 1.0000x reference)
#include <cuda_runtime.h>

#define N_NODES 100000
#define K 32
#define D 64
#define NEG_SLOPE 0.2f

// Persistent scratch (allowed: __device__ globals, no allocation).
// All of these are fully rewritten by k_gemm on every launch -> replay-safe.
__device__ __align__(128) float g_h[(size_t)N_NODES * D];
__device__ __align__(128) float g_acc[(size_t)N_NODES * D];
__device__ float g_si[N_NODES];
__device__ float g_sj[N_NODES];
__device__ float g_denom[N_NODES];

// ---------------------------------------------------------------------------
// Kernel 1: h = embed @ W (warp-per-row, W staged in smem as paired float2),
// s_i = h.a_i, s_j = h.a_j, and self-loop init of acc/denom.
// ---------------------------------------------------------------------------
__global__ void __launch_bounds__(256) k_gemm(const float* __restrict__ embed,
                                              const float* __restrict__ W,
                                              const float* __restrict__ att) {
    // ws[k][c] = (W[k][c], W[k][c+32]) : lane c reads both of its columns in
    // one LDS.64, conflict-free (stride 8B across 32 lanes).
    __shared__ float2 ws[64][32];
    __shared__ float s_att[2 * D];

    int t = threadIdx.x;
    for (int idx = t; idx < 64 * 64; idx += 256) {
        int k = idx >> 6;
        int c = idx & 63;
        float v = W[idx];
        if (c < 32) ws[k][c].x = v;
        else        ws[k][c - 32].y = v;
    }
    if (t < 2 * D) s_att[t] = att[t];
    __syncthreads();

    int lane = t & 31;
    int warp = t >> 5;
    int row  = blockIdx.x * 8 + warp;
    if (row >= N_NODES) return;

    // lane l holds embed[row][2l], embed[row][2l+1]
    float2 ev = reinterpret_cast<const float2*>(embed + (size_t)row * D)[lane];

    float2 acc = make_float2(0.f, 0.f);
#pragma unroll
    for (int k = 0; k < 32; k++) {
        float ex = __shfl_sync(0xffffffffu, ev.x, k);   // embed[row][2k]
        float ey = __shfl_sync(0xffffffffu, ev.y, k);   // embed[row][2k+1]
        float2 w0 = ws[2 * k][lane];
        float2 w1 = ws[2 * k + 1][lane];
        acc.x += ex * w0.x + ey * w1.x;   // col = lane
        acc.y += ex * w0.y + ey * w1.y;   // col = lane + 32
    }

    size_t base = (size_t)row * D;
    g_h[base + lane]      = acc.x;
    g_h[base + lane + 32] = acc.y;

    float si = acc.x * s_att[lane]     + acc.y * s_att[lane + 32];
    float sj = acc.x * s_att[D + lane] + acc.y * s_att[D + lane + 32];
#pragma unroll
    for (int o = 16; o > 0; o >>= 1) {
        si += __shfl_xor_sync(0xffffffffu, si, o);
        sj += __shfl_xor_sync(0xffffffffu, sj, o);
    }
    // si, sj now uniform across the warp.
    if (lane == 0) {
        g_si[row] = si;
        g_sj[row] = sj;
    }

    // Self-loop edge (always valid): softmax computed WITHOUT max-shift
    // (shift-invariant; alpha is O(1) here so exp never overflows).
    float alpha = si + sj;
    alpha = (alpha >= 0.f) ? alpha : NEG_SLOPE * alpha;
    float es = __expf(alpha);
    if (lane == 0) g_denom[row] = es;
    g_acc[base + lane]      = acc.x * es;
    g_acc[base + lane + 32] = acc.y * es;
}

// ---------------------------------------------------------------------------
// Kernel 2: edge scatter. One warp per source node i: the 32 lanes own the 32
// out-edges. denom via scalar atomic, row payload via float4 vector atomics
// (2 edges per warp-instruction: lanes 0-15 -> edge 2j, lanes 16-31 -> 2j+1).
// ---------------------------------------------------------------------------
__global__ void __launch_bounds__(256) k_edges(const int* __restrict__ edges) {
    int lane = threadIdx.x & 31;
    int warp = threadIdx.x >> 5;
    int i = blockIdx.x * 8 + warp;
    if (i >= N_NODES) return;

    int dst  = edges[(size_t)i * K + lane];
    float sj = g_sj[i];
    float si = __ldg(&g_si[dst]);
    float alpha = si + sj;
    alpha = (alpha >= 0.f) ? alpha : NEG_SLOPE * alpha;
    float e = (dst != i) ? __expf(alpha) : 0.f;   // invalid (self) edges drop out

    if (e != 0.f) atomicAdd(&g_denom[dst], e);

    // Each half-warp holds the full h[i] row as float4 chunks.
    const float4* hrow = reinterpret_cast<const float4*>(g_h + (size_t)i * D);
    float4 h4 = hrow[lane & 15];
    int half = lane >> 4;

#pragma unroll
    for (int j = 0; j < 16; j++) {
        int   jj = 2 * j + half;
        float ej = __shfl_sync(0xffffffffu, e, jj);
        int   dj = __shfl_sync(0xffffffffu, dst, jj);
        if (ej != 0.f) {   // uniform per half-warp
            float4 v = make_float4(h4.x * ej, h4.y * ej, h4.z * ej, h4.w * ej);
            atomicAdd(reinterpret_cast<float4*>(g_acc + (size_t)dj * D) + (lane & 15), v);
        }
    }
}

// ---------------------------------------------------------------------------
// Kernel 3: finalize. out = normalize(acc/denom + bias).
// ---------------------------------------------------------------------------
__global__ void __launch_bounds__(256) k_final(const float* __restrict__ bias,
                                               float* __restrict__ out) {
    int lane = threadIdx.x & 31;
    int warp = threadIdx.x >> 5;
    int i = blockIdx.x * 8 + warp;
    if (i >= N_NODES) return;

    size_t base = (size_t)i * D;
    float inv = 1.f / (g_denom[i] + 1e-16f);
    float vx = g_acc[base + lane]      * inv + bias[lane];
    float vy = g_acc[base + lane + 32] * inv + bias[lane + 32];

    float ss = vx * vx + vy * vy;
#pragma unroll
    for (int o = 16; o > 0; o >>= 1)
        ss += __shfl_xor_sync(0xffffffffu, ss, o);

    float scale = 1.f / fmaxf(sqrtf(ss), 1e-12f);
    out[base + lane]      = vx * scale;
    out[base + lane + 32] = vy * scale;
}

// ---------------------------------------------------------------------------
extern "C" void kernel_launch(void* const* d_in, const int* in_sizes, int n_in,
                              void* d_out, int out_size) {
    const float* embed = (const float*)d_in[0];
    const float* W     = (const float*)d_in[1];
    const float* att   = (const float*)d_in[2];
    const float* bias  = (const float*)d_in[3];
    const int*   edges = (const int*)d_in[7];
    float* out = (float*)d_out;

    int blocks = (N_NODES + 7) / 8;   // 8 warps/block, warp-per-node
    k_gemm <<<blocks, 256>>>(embed, W, att);
    k_edges<<<blocks, 256>>>(edges);
    k_final<<<blocks, 256>>>(bias, out);
}

// round 2
// speedup vs baseline: 1.4631x; 1.4631x over previous
#include <cuda_runtime.h>

#define N_NODES 100000
#define N_PAD   100032           // 1563 blocks * 64 rows
#define K 32
#define D 64
#define CAP 96                   // per-dst bucket capacity (Poisson(32) tail ~1e-18)
#define NEG_SLOPE 0.2f

// Persistent scratch — fully rewritten every launch (replay-safe).
__device__ __align__(128) float g_h[(size_t)N_PAD * D];
__device__ float g_si[N_PAD];
__device__ float g_sj[N_PAD];
__device__ int   g_cnt[N_PAD];
__device__ __align__(128) int2  g_bkt[(size_t)N_NODES * CAP];

// ---------------------------------------------------------------------------
// f32x2 packed helpers (SASS FFMA2 — only reachable via PTX fma.rn.f32x2)
// ---------------------------------------------------------------------------
static __device__ __forceinline__ unsigned long long dup2(float x) {
    unsigned long long r;
    unsigned u = __float_as_uint(x);
    asm("mov.b64 %0, {%1, %1};" : "=l"(r) : "r"(u));
    return r;
}
static __device__ __forceinline__ unsigned long long fma2(unsigned long long a,
                                                          unsigned long long b,
                                                          unsigned long long c) {
    unsigned long long d;
    asm("fma.rn.f32x2 %0, %1, %2, %3;" : "=l"(d) : "l"(a), "l"(b), "l"(c));
    return d;
}
static __device__ __forceinline__ void unpack2(unsigned long long v, float& lo, float& hi) {
    unsigned a, b;
    asm("mov.b64 {%0, %1}, %2;" : "=r"(a), "=r"(b) : "l"(v));
    lo = __uint_as_float(a);
    hi = __uint_as_float(b);
}

// ---------------------------------------------------------------------------
// Kernel 1: h = embed @ W, s_i, s_j. 8 warps/block, 8 rows/warp (64 rows/blk).
// W tile:     ws4[kk][c]  = (W[2kk][c], W[2kk][c+32], W[2kk+1][c], W[2kk+1][c+32])
// embed tile: es4[kk][rp] = (E[2rp][2kk], E[2rp+1][2kk], E[2rp][2kk+1], E[2rp+1][2kk+1])
//   -> low/high 64-bit halves of es4 are row-pair-packed operands for FFMA2.
// Also zeroes g_cnt for the fill phase.
// ---------------------------------------------------------------------------
__global__ void __launch_bounds__(256) k_gemm(const float* __restrict__ embed,
                                              const float* __restrict__ W,
                                              const float* __restrict__ att) {
    __shared__ float4 ws4[32][33];   // +1 pad: avoids 16-way store conflicts on fill
    __shared__ float4 es4[32][33];

    int t = threadIdx.x;
    int base = blockIdx.x * 64;

    for (int idx = t; idx < 4096; idx += 256) {
        int k = idx >> 6, c = idx & 63;
        reinterpret_cast<float*>(&ws4[k >> 1][c & 31])[2 * (k & 1) + (c >> 5)] = W[idx];
    }
    for (int idx = t; idx < 4096; idx += 256) {
        int r = idx >> 6, k = idx & 63;
        int row = base + r;
        float v = (row < N_NODES) ? embed[(size_t)row * D + k] : 0.f;
        reinterpret_cast<float*>(&es4[k >> 1][r >> 1])[(r & 1) + 2 * (k & 1)] = v;
    }
    if (t < 64) g_cnt[base + t] = 0;
    __syncthreads();

    int lane = t & 31, warp = t >> 5;
    int rp0 = warp * 4;              // 4 row-pairs = 8 rows per warp

    unsigned long long acc0[4] = {0ull, 0ull, 0ull, 0ull};  // col = lane
    unsigned long long acc1[4] = {0ull, 0ull, 0ull, 0ull};  // col = lane + 32

#pragma unroll 4
    for (int kk = 0; kk < 32; kk++) {
        float4 wv = ws4[kk][lane];                    // LDS.128, conflict-free
        unsigned long long wa0 = dup2(wv.x), wa1 = dup2(wv.y);
        unsigned long long wb0 = dup2(wv.z), wb1 = dup2(wv.w);
#pragma unroll
        for (int rp = 0; rp < 4; rp++) {
            ulonglong2 ev = *reinterpret_cast<const ulonglong2*>(&es4[kk][rp0 + rp]); // broadcast
            acc0[rp] = fma2(ev.x, wa0, acc0[rp]);
            acc1[rp] = fma2(ev.x, wa1, acc1[rp]);
            acc0[rp] = fma2(ev.y, wb0, acc0[rp]);
            acc1[rp] = fma2(ev.y, wb1, acc1[rp]);
        }
    }

    float ai0 = __ldg(&att[lane]),     ai1 = __ldg(&att[lane + 32]);
    float aj0 = __ldg(&att[D + lane]), aj1 = __ldg(&att[D + lane + 32]);

#pragma unroll
    for (int rp = 0; rp < 4; rp++) {
        float x0, x1, y0, y1;
        unpack2(acc0[rp], x0, x1);   // rows 2rp, 2rp+1, col = lane
        unpack2(acc1[rp], y0, y1);   // rows 2rp, 2rp+1, col = lane+32
        int r0 = base + warp * 8 + 2 * rp;

        g_h[(size_t)r0 * D + lane]            = x0;
        g_h[(size_t)r0 * D + lane + 32]       = y0;
        g_h[(size_t)(r0 + 1) * D + lane]      = x1;
        g_h[(size_t)(r0 + 1) * D + lane + 32] = y1;

        float si0 = x0 * ai0 + y0 * ai1, sj0 = x0 * aj0 + y0 * aj1;
        float si1 = x1 * ai0 + y1 * ai1, sj1 = x1 * aj0 + y1 * aj1;
#pragma unroll
        for (int o = 16; o > 0; o >>= 1) {
            si0 += __shfl_xor_sync(0xffffffffu, si0, o);
            sj0 += __shfl_xor_sync(0xffffffffu, sj0, o);
            si1 += __shfl_xor_sync(0xffffffffu, si1, o);
            sj1 += __shfl_xor_sync(0xffffffffu, sj1, o);
        }
        if (lane == 0) {
            g_si[r0] = si0;     g_sj[r0] = sj0;
            g_si[r0 + 1] = si1; g_sj[r0 + 1] = sj1;
        }
    }
}

// ---------------------------------------------------------------------------
// Kernel 2: fill per-dst buckets with (src, e). Warp per src node.
// Softmax without max-shift (shift-invariant; alpha is O(1) for these inputs).
// ---------------------------------------------------------------------------
__global__ void __launch_bounds__(256) k_fill(const int* __restrict__ edges) {
    int lane = threadIdx.x & 31;
    int i = blockIdx.x * 8 + (threadIdx.x >> 5);

    int dst  = edges[(size_t)i * K + lane];   // coalesced
    float sj = g_sj[i];                       // broadcast
    float si = g_si[dst];                     // random (L1/L2 hit)
    float a  = si + sj;
    a = (a >= 0.f) ? a : NEG_SLOPE * a;

    if (dst != i) {                           // invalid (self) K-edges drop out
        float e = __expf(a);
        int pos = atomicAdd(&g_cnt[dst], 1);
        if (pos < CAP)
            g_bkt[(size_t)dst * CAP + pos] = make_int2(i, __float_as_int(e));
    }
}

// ---------------------------------------------------------------------------
// Kernel 3: gather + finalize. Warp per dst node; lane owns cols (2l, 2l+1).
// out = normalize((h[dst]*e_self + sum h[src]*e) / denom + bias)
// ---------------------------------------------------------------------------
__global__ void __launch_bounds__(256) k_gather(const float* __restrict__ bias,
                                                float* __restrict__ out) {
    int lane = threadIdx.x & 31;
    int dst  = blockIdx.x * 8 + (threadIdx.x >> 5);

    // Self loop (always valid)
    float a = g_si[dst] + g_sj[dst];
    a = (a >= 0.f) ? a : NEG_SLOPE * a;
    float es = __expf(a);

    float2 hd = *reinterpret_cast<const float2*>(g_h + (size_t)dst * D + 2 * lane);
    float accx = hd.x * es, accy = hd.y * es, den = es;

    int deg = min(g_cnt[dst], CAP);
    const int2* bp = g_bkt + (size_t)dst * CAP;
    int2 e0 = (lane < deg)      ? bp[lane]      : make_int2(0, 0);
    int2 e1 = (lane + 32 < deg) ? bp[lane + 32] : make_int2(0, 0);
    int2 e2 = (lane + 64 < deg) ? bp[lane + 64] : make_int2(0, 0);

#define SEG(ent, cnt)                                                                  \
    _Pragma("unroll 4")                                                                \
    for (int j = 0; j < (cnt); j++) {                                                  \
        int   s = __shfl_sync(0xffffffffu, (ent).x, j);                                \
        float e = __int_as_float(__shfl_sync(0xffffffffu, (ent).y, j));                \
        float2 hv = *reinterpret_cast<const float2*>(g_h + (size_t)s * D + 2 * lane);  \
        accx += hv.x * e; accy += hv.y * e; den += e;                                  \
    }

    SEG(e0, min(deg, 32));
    if (deg > 32) { SEG(e1, min(deg - 32, 32)); }
    if (deg > 64) { SEG(e2, deg - 64); }
#undef SEG

    float inv = 1.f / (den + 1e-16f);
    float vx = accx * inv + __ldg(&bias[2 * lane]);
    float vy = accy * inv + __ldg(&bias[2 * lane + 1]);

    float ss = vx * vx + vy * vy;
#pragma unroll
    for (int o = 16; o > 0; o >>= 1)
        ss += __shfl_xor_sync(0xffffffffu, ss, o);

    float scale = 1.f / fmaxf(sqrtf(ss), 1e-12f);
    *reinterpret_cast<float2*>(out + (size_t)dst * D + 2 * lane) =
        make_float2(vx * scale, vy * scale);
}

// ---------------------------------------------------------------------------
extern "C" void kernel_launch(void* const* d_in, const int* in_sizes, int n_in,
                              void* d_out, int out_size) {
    const float* embed = (const float*)d_in[0];
    const float* W     = (const float*)d_in[1];
    const float* att   = (const float*)d_in[2];
    const float* bias  = (const float*)d_in[3];
    const int*   edges = (const int*)d_in[7];
    float* out = (float*)d_out;

    k_gemm  <<<(N_NODES + 63) / 64, 256>>>(embed, W, att);   // 1563 blocks
    k_fill  <<<N_NODES / 8, 256>>>(edges);                   // 12500 blocks
    k_gather<<<N_NODES / 8, 256>>>(bias, out);               // 12500 blocks
}

// round 3
// speedup vs baseline: 1.5533x; 1.0617x over previous
#include <cuda_runtime.h>
#include <cuda_fp16.h>

#define N_NODES 100000
#define N_PAD   100032           // 1563 blocks * 64 rows
#define K 32
#define D 64
#define CAP 96                   // per-dst bucket capacity (Poisson(32) tail ~1e-18)
#define NEG_SLOPE 0.2f

// Persistent scratch — fully rewritten every launch (replay-safe).
__device__ __align__(128) __half g_h16[(size_t)N_PAD * D];
__device__ float g_si[N_PAD];
__device__ float g_sj[N_PAD];
__device__ int   g_cnt[N_PAD];
__device__ __align__(128) int2  g_bkt[(size_t)N_NODES * CAP];

// ---------------------------------------------------------------------------
// f32x2 packed helpers (SASS FFMA2 — only reachable via PTX fma.rn.f32x2)
// ---------------------------------------------------------------------------
static __device__ __forceinline__ unsigned long long dup2(float x) {
    unsigned long long r;
    unsigned u = __float_as_uint(x);
    asm("mov.b64 %0, {%1, %1};" : "=l"(r) : "r"(u));
    return r;
}
static __device__ __forceinline__ unsigned long long fma2(unsigned long long a,
                                                          unsigned long long b,
                                                          unsigned long long c) {
    unsigned long long d;
    asm("fma.rn.f32x2 %0, %1, %2, %3;" : "=l"(d) : "l"(a), "l"(b), "l"(c));
    return d;
}
static __device__ __forceinline__ void unpack2(unsigned long long v, float& lo, float& hi) {
    unsigned a, b;
    asm("mov.b64 {%0, %1}, %2;" : "=r"(a), "=r"(b) : "l"(v));
    lo = __uint_as_float(a);
    hi = __uint_as_float(b);
}

// ---------------------------------------------------------------------------
// Kernel 1: h = embed @ W (fp16 out), s_i, s_j. 8 warps/blk, 8 rows/warp.
// ---------------------------------------------------------------------------
__global__ void __launch_bounds__(256) k_gemm(const float* __restrict__ embed,
                                              const float* __restrict__ W,
                                              const float* __restrict__ att) {
    __shared__ float4 ws4[32][33];
    __shared__ float4 es4[32][33];

    int t = threadIdx.x;
    int base = blockIdx.x * 64;

    for (int idx = t; idx < 4096; idx += 256) {
        int k = idx >> 6, c = idx & 63;
        reinterpret_cast<float*>(&ws4[k >> 1][c & 31])[2 * (k & 1) + (c >> 5)] = W[idx];
    }
    for (int idx = t; idx < 4096; idx += 256) {
        int r = idx >> 6, k = idx & 63;
        int row = base + r;
        float v = (row < N_NODES) ? embed[(size_t)row * D + k] : 0.f;
        reinterpret_cast<float*>(&es4[k >> 1][r >> 1])[(r & 1) + 2 * (k & 1)] = v;
    }
    if (t < 64) g_cnt[base + t] = 0;
    __syncthreads();

    int lane = t & 31, warp = t >> 5;
    int rp0 = warp * 4;              // 4 row-pairs = 8 rows per warp

    unsigned long long acc0[4] = {0ull, 0ull, 0ull, 0ull};  // col = lane
    unsigned long long acc1[4] = {0ull, 0ull, 0ull, 0ull};  // col = lane + 32

#pragma unroll 4
    for (int kk = 0; kk < 32; kk++) {
        float4 wv = ws4[kk][lane];                    // LDS.128, conflict-free
        unsigned long long wa0 = dup2(wv.x), wa1 = dup2(wv.y);
        unsigned long long wb0 = dup2(wv.z), wb1 = dup2(wv.w);
#pragma unroll
        for (int rp = 0; rp < 4; rp++) {
            ulonglong2 ev = *reinterpret_cast<const ulonglong2*>(&es4[kk][rp0 + rp]); // broadcast
            acc0[rp] = fma2(ev.x, wa0, acc0[rp]);
            acc1[rp] = fma2(ev.x, wa1, acc1[rp]);
            acc0[rp] = fma2(ev.y, wb0, acc0[rp]);
            acc1[rp] = fma2(ev.y, wb1, acc1[rp]);
        }
    }

    float ai0 = __ldg(&att[lane]),     ai1 = __ldg(&att[lane + 32]);
    float aj0 = __ldg(&att[D + lane]), aj1 = __ldg(&att[D + lane + 32]);

#pragma unroll
    for (int rp = 0; rp < 4; rp++) {
        float x0, x1, y0, y1;
        unpack2(acc0[rp], x0, x1);   // rows 2rp, 2rp+1, col = lane
        unpack2(acc1[rp], y0, y1);   // rows 2rp, 2rp+1, col = lane+32
        int r0 = base + warp * 8 + 2 * rp;

        g_h16[(size_t)r0 * D + lane]            = __float2half_rn(x0);
        g_h16[(size_t)r0 * D + lane + 32]       = __float2half_rn(y0);
        g_h16[(size_t)(r0 + 1) * D + lane]      = __float2half_rn(x1);
        g_h16[(size_t)(r0 + 1) * D + lane + 32] = __float2half_rn(y1);

        float si0 = x0 * ai0 + y0 * ai1, sj0 = x0 * aj0 + y0 * aj1;
        float si1 = x1 * ai0 + y1 * ai1, sj1 = x1 * aj0 + y1 * aj1;
#pragma unroll
        for (int o = 16; o > 0; o >>= 1) {
            si0 += __shfl_xor_sync(0xffffffffu, si0, o);
            sj0 += __shfl_xor_sync(0xffffffffu, sj0, o);
            si1 += __shfl_xor_sync(0xffffffffu, si1, o);
            sj1 += __shfl_xor_sync(0xffffffffu, sj1, o);
        }
        if (lane == 0) {
            g_si[r0] = si0;     g_sj[r0] = sj0;
            g_si[r0 + 1] = si1; g_sj[r0 + 1] = sj1;
        }
    }
}

// ---------------------------------------------------------------------------
// Kernel 2: fill per-dst buckets with (src, e). Warp per src node.
// Softmax without max-shift (shift-invariant; alpha is O(1) for these inputs).
// ---------------------------------------------------------------------------
__global__ void __launch_bounds__(256) k_fill(const int* __restrict__ edges) {
    int lane = threadIdx.x & 31;
    int i = blockIdx.x * 8 + (threadIdx.x >> 5);

    int dst  = edges[(size_t)i * K + lane];   // coalesced
    float sj = g_sj[i];                       // broadcast
    float si = __ldg(&g_si[dst]);             // random (L1/L2 hit)
    float a  = si + sj;
    a = (a >= 0.f) ? a : NEG_SLOPE * a;

    if (dst != i) {                           // invalid (self) K-edges drop out
        float e = __expf(a);
        int pos = atomicAdd(&g_cnt[dst], 1);
        if (pos < CAP)
            g_bkt[(size_t)dst * CAP + pos] = make_int2(i, __float_as_int(e));
    }
}

// ---------------------------------------------------------------------------
// Kernel 3: gather + finalize. Warp per dst node; lane owns cols [4c..4c+3],
// c = lane&15. Two edges per iteration (one per half-warp, fp16 row loads).
// out = normalize((h[dst]*e_self + sum h[src]*e) / denom + bias)
// ---------------------------------------------------------------------------
__global__ void __launch_bounds__(256) k_gather(const float* __restrict__ bias,
                                                float* __restrict__ out) {
    int lane = threadIdx.x & 31;
    int c    = lane & 15;
    int half = lane >> 4;
    int dst  = blockIdx.x * 8 + (threadIdx.x >> 5);

    float4 acc = make_float4(0.f, 0.f, 0.f, 0.f);
    float  den = 0.f;

    // Self loop (always valid) — only half 0 contributes (halves are merged later).
    {
        float a = g_si[dst] + g_sj[dst];
        a = (a >= 0.f) ? a : NEG_SLOPE * a;
        float es = __expf(a);
        if (half == 0) {
            uint2 u = reinterpret_cast<const uint2*>(g_h16 + (size_t)dst * D)[c];
            float2 fa = __half22float2(*reinterpret_cast<__half2*>(&u.x));
            float2 fb = __half22float2(*reinterpret_cast<__half2*>(&u.y));
            acc.x = fa.x * es; acc.y = fa.y * es;
            acc.z = fb.x * es; acc.w = fb.y * es;
            den = es;
        }
    }

    int deg = min(g_cnt[dst], CAP);
    const int2* bp = g_bkt + (size_t)dst * CAP;
    int2 e0 = (lane < deg)      ? bp[lane]      : make_int2(0, 0);
    int2 e1 = (lane + 32 < deg) ? bp[lane + 32] : make_int2(0, 0);
    int2 e2 = (lane + 64 < deg) ? bp[lane + 64] : make_int2(0, 0);

    // Per segment: iteration j handles edges 2j (half 0) and 2j+1 (half 1).
    // Padding entries carry e==0 (exp>0 for real edges) -> skipped uniformly
    // within each half-warp.
#define SEG(ent, cnt)                                                              \
    {                                                                              \
        int iters = ((cnt) + 1) >> 1;                                              \
        _Pragma("unroll 4")                                                        \
        for (int j = 0; j < iters; j++) {                                          \
            int   jj = 2 * j + half;                                               \
            int   s = __shfl_sync(0xffffffffu, (ent).x, jj);                       \
            float e = __int_as_float(__shfl_sync(0xffffffffu, (ent).y, jj));       \
            if (e != 0.f) {                                                        \
                uint2 u = reinterpret_cast<const uint2*>(g_h16 + (size_t)s * D)[c];\
                float2 fa = __half22float2(*reinterpret_cast<__half2*>(&u.x));     \
                float2 fb = __half22float2(*reinterpret_cast<__half2*>(&u.y));     \
                acc.x += fa.x * e; acc.y += fa.y * e;                              \
                acc.z += fb.x * e; acc.w += fb.y * e;                              \
                den += e;                                                          \
            }                                                                      \
        }                                                                          \
    }

    SEG(e0, min(deg, 32));
    if (deg > 32) SEG(e1, min(deg - 32, 32));
    if (deg > 64) SEG(e2, deg - 64);
#undef SEG

    // Merge the two half-warp partial sums (cols are duplicated across halves).
    acc.x += __shfl_xor_sync(0xffffffffu, acc.x, 16);
    acc.y += __shfl_xor_sync(0xffffffffu, acc.y, 16);
    acc.z += __shfl_xor_sync(0xffffffffu, acc.z, 16);
    acc.w += __shfl_xor_sync(0xffffffffu, acc.w, 16);
    den   += __shfl_xor_sync(0xffffffffu, den,   16);

    float4 bv = __ldg(reinterpret_cast<const float4*>(bias) + c);
    float inv = 1.f / (den + 1e-16f);
    float vx = acc.x * inv + bv.x;
    float vy = acc.y * inv + bv.y;
    float vz = acc.z * inv + bv.z;
    float vw = acc.w * inv + bv.w;

    float ss = vx * vx + vy * vy + vz * vz + vw * vw;
#pragma unroll
    for (int o = 8; o > 0; o >>= 1)
        ss += __shfl_xor_sync(0xffffffffu, ss, o);

    float scale = 1.f / fmaxf(sqrtf(ss), 1e-12f);
    if (half == 0) {
        reinterpret_cast<float4*>(out + (size_t)dst * D)[c] =
            make_float4(vx * scale, vy * scale, vz * scale, vw * scale);
    }
}

// ---------------------------------------------------------------------------
extern "C" void kernel_launch(void* const* d_in, const int* in_sizes, int n_in,
                              void* d_out, int out_size) {
    const float* embed = (const float*)d_in[0];
    const float* W     = (const float*)d_in[1];
    const float* att   = (const float*)d_in[2];
    const float* bias  = (const float*)d_in[3];
    const int*   edges = (const int*)d_in[7];
    float* out = (float*)d_out;

    k_gemm  <<<(N_NODES + 63) / 64, 256>>>(embed, W, att);   // 1563 blocks
    k_fill  <<<N_NODES / 8, 256>>>(edges);                   // 12500 blocks
    k_gather<<<N_NODES / 8, 256>>>(bias, out);               // 12500 blocks
}

// round 4
// speedup vs baseline: 1.7270x; 1.1118x over previous
#include <cuda_runtime.h>
#include <cuda_fp16.h>

#define N_NODES 100000
#define N_PAD   100032           // 1563 blocks * 64 rows
#define K 32
#define D 64
#define CAP 96                   // per-dst bucket capacity (Poisson(32) tail ~1e-18)
#define NEG_SLOPE 0.2f

// Persistent scratch — fully rewritten every launch (replay-safe).
__device__ __align__(128) __half g_h16[(size_t)N_PAD * D];
__device__ float g_si[N_PAD];
__device__ float g_sj[N_PAD];
__device__ int   g_cnt[N_PAD];
__device__ __align__(128) int2  g_bkt[(size_t)N_NODES * CAP];

// ---------------------------------------------------------------------------
// f32x2 packed helpers (SASS FFMA2 — only reachable via PTX fma.rn.f32x2)
// ---------------------------------------------------------------------------
static __device__ __forceinline__ unsigned long long dup2(float x) {
    unsigned long long r;
    unsigned u = __float_as_uint(x);
    asm("mov.b64 %0, {%1, %1};" : "=l"(r) : "r"(u));
    return r;
}
static __device__ __forceinline__ unsigned long long fma2(unsigned long long a,
                                                          unsigned long long b,
                                                          unsigned long long c) {
    unsigned long long d;
    asm("fma.rn.f32x2 %0, %1, %2, %3;" : "=l"(d) : "l"(a), "l"(b), "l"(c));
    return d;
}
static __device__ __forceinline__ void unpack2(unsigned long long v, float& lo, float& hi) {
    unsigned a, b;
    asm("mov.b64 {%0, %1}, %2;" : "=r"(a), "=r"(b) : "l"(v));
    lo = __uint_as_float(a);
    hi = __uint_as_float(b);
}

// ---------------------------------------------------------------------------
// Kernel 1: h = embed @ W (fp16 out), s_i, s_j. 8 warps/blk, 8 rows/warp.
// ---------------------------------------------------------------------------
__global__ void __launch_bounds__(256) k_gemm(const float* __restrict__ embed,
                                              const float* __restrict__ W,
                                              const float* __restrict__ att) {
    __shared__ float4 ws4[32][33];
    __shared__ float4 es4[32][33];

    int t = threadIdx.x;
    int base = blockIdx.x * 64;

    for (int idx = t; idx < 4096; idx += 256) {
        int k = idx >> 6, c = idx & 63;
        reinterpret_cast<float*>(&ws4[k >> 1][c & 31])[2 * (k & 1) + (c >> 5)] = W[idx];
    }
    for (int idx = t; idx < 4096; idx += 256) {
        int r = idx >> 6, k = idx & 63;
        int row = base + r;
        float v = (row < N_NODES) ? embed[(size_t)row * D + k] : 0.f;
        reinterpret_cast<float*>(&es4[k >> 1][r >> 1])[(r & 1) + 2 * (k & 1)] = v;
    }
    if (t < 64) g_cnt[base + t] = 0;
    __syncthreads();

    int lane = t & 31, warp = t >> 5;
    int rp0 = warp * 4;              // 4 row-pairs = 8 rows per warp

    unsigned long long acc0[4] = {0ull, 0ull, 0ull, 0ull};  // col = lane
    unsigned long long acc1[4] = {0ull, 0ull, 0ull, 0ull};  // col = lane + 32

#pragma unroll 8
    for (int kk = 0; kk < 32; kk++) {
        float4 wv = ws4[kk][lane];                    // LDS.128, conflict-free
        unsigned long long wa0 = dup2(wv.x), wa1 = dup2(wv.y);
        unsigned long long wb0 = dup2(wv.z), wb1 = dup2(wv.w);
#pragma unroll
        for (int rp = 0; rp < 4; rp++) {
            ulonglong2 ev = *reinterpret_cast<const ulonglong2*>(&es4[kk][rp0 + rp]); // broadcast
            acc0[rp] = fma2(ev.x, wa0, acc0[rp]);
            acc1[rp] = fma2(ev.x, wa1, acc1[rp]);
            acc0[rp] = fma2(ev.y, wb0, acc0[rp]);
            acc1[rp] = fma2(ev.y, wb1, acc1[rp]);
        }
    }

    float ai0 = __ldg(&att[lane]),     ai1 = __ldg(&att[lane + 32]);
    float aj0 = __ldg(&att[D + lane]), aj1 = __ldg(&att[D + lane + 32]);

#pragma unroll
    for (int rp = 0; rp < 4; rp++) {
        float x0, x1, y0, y1;
        unpack2(acc0[rp], x0, x1);   // rows 2rp, 2rp+1, col = lane
        unpack2(acc1[rp], y0, y1);   // rows 2rp, 2rp+1, col = lane+32
        int r0 = base + warp * 8 + 2 * rp;

        g_h16[(size_t)r0 * D + lane]            = __float2half_rn(x0);
        g_h16[(size_t)r0 * D + lane + 32]       = __float2half_rn(y0);
        g_h16[(size_t)(r0 + 1) * D + lane]      = __float2half_rn(x1);
        g_h16[(size_t)(r0 + 1) * D + lane + 32] = __float2half_rn(y1);

        float si0 = x0 * ai0 + y0 * ai1, sj0 = x0 * aj0 + y0 * aj1;
        float si1 = x1 * ai0 + y1 * ai1, sj1 = x1 * aj0 + y1 * aj1;
#pragma unroll
        for (int o = 16; o > 0; o >>= 1) {
            si0 += __shfl_xor_sync(0xffffffffu, si0, o);
            sj0 += __shfl_xor_sync(0xffffffffu, sj0, o);
            si1 += __shfl_xor_sync(0xffffffffu, si1, o);
            sj1 += __shfl_xor_sync(0xffffffffu, sj1, o);
        }
        if (lane == 0) {
            g_si[r0] = si0;     g_sj[r0] = sj0;
            g_si[r0 + 1] = si1; g_sj[r0 + 1] = sj1;
        }
    }
}

// ---------------------------------------------------------------------------
// Kernel 2: fill per-dst buckets with (src, e). Warp per src node.
// Softmax without max-shift (shift-invariant; alpha is O(1) for these inputs).
// ---------------------------------------------------------------------------
__global__ void __launch_bounds__(256) k_fill(const int* __restrict__ edges) {
    int lane = threadIdx.x & 31;
    int i = blockIdx.x * 8 + (threadIdx.x >> 5);

    int dst  = edges[(size_t)i * K + lane];   // coalesced
    float sj = g_sj[i];                       // broadcast
    float si = __ldg(&g_si[dst]);             // random (L1/L2 hit)
    float a  = si + sj;
    a = (a >= 0.f) ? a : NEG_SLOPE * a;

    if (dst != i) {                           // invalid (self) K-edges drop out
        float e = __expf(a);
        int pos = atomicAdd(&g_cnt[dst], 1);
        if (pos < CAP)
            g_bkt[(size_t)dst * CAP + pos] = make_int2(i, __float_as_int(e));
    }
}

// ---------------------------------------------------------------------------
// Kernel 3: gather + finalize. Warp per dst node; lane owns cols [4c..4c+3],
// c = lane&15, two edges per iteration (one per half-warp).
// Bucket (+ self-loop entry + zero pad) staged in smem -> branch-free inner
// loop with independent LDGs: LDS.64 broadcast -> LDG.64 -> FMA.
// Pad entries carry e=0 and src=0 (row 0 is valid, hot in cache; adds 0).
// out = normalize((sum h[src]*e) / denom + bias)
// ---------------------------------------------------------------------------
__global__ void __launch_bounds__(256) k_gather(const float* __restrict__ bias,
                                                float* __restrict__ out) {
    __shared__ int2 sb[8][CAP + 2];

    int lane = threadIdx.x & 31;
    int w    = threadIdx.x >> 5;
    int c    = lane & 15;
    int half = lane >> 4;
    int dst  = blockIdx.x * 8 + w;

    int deg = min(g_cnt[dst], CAP);
    const int2* bp = g_bkt + (size_t)dst * CAP;

    // Stage bucket entries into smem (coalesced).
    for (int j = lane; j < deg; j += 32)
        sb[w][j] = bp[j];

    // Self loop (always valid) appended at index deg; zero pad at deg+1.
    float a = g_si[dst] + g_sj[dst];
    a = (a >= 0.f) ? a : NEG_SLOPE * a;
    float es = __expf(a);
    if (lane == 0) {
        sb[w][deg]     = make_int2(dst, __float_as_int(es));
        sb[w][deg + 1] = make_int2(0, 0);
    }
    __syncwarp();

    float4 acc = make_float4(0.f, 0.f, 0.f, 0.f);
    float  den = 0.f;

    int iters = (deg + 2) >> 1;          // ceil((deg+1)/2) entries incl. self
#pragma unroll 4
    for (int j = 0; j < iters; j++) {
        int2 ent = sb[w][2 * j + half];  // LDS.64, 2 broadcast addrs
        float e = __int_as_float(ent.y);
        uint2 u = reinterpret_cast<const uint2*>(g_h16 + (size_t)ent.x * D)[c];
        float2 fa = __half22float2(*reinterpret_cast<__half2*>(&u.x));
        float2 fb = __half22float2(*reinterpret_cast<__half2*>(&u.y));
        acc.x += fa.x * e; acc.y += fa.y * e;
        acc.z += fb.x * e; acc.w += fb.y * e;
        den += e;
    }

    // Merge the two half-warp partial sums (cols duplicated across halves).
    acc.x += __shfl_xor_sync(0xffffffffu, acc.x, 16);
    acc.y += __shfl_xor_sync(0xffffffffu, acc.y, 16);
    acc.z += __shfl_xor_sync(0xffffffffu, acc.z, 16);
    acc.w += __shfl_xor_sync(0xffffffffu, acc.w, 16);
    den   += __shfl_xor_sync(0xffffffffu, den,   16);

    float4 bv = __ldg(reinterpret_cast<const float4*>(bias) + c);
    float inv = 1.f / (den + 1e-16f);
    float vx = acc.x * inv + bv.x;
    float vy = acc.y * inv + bv.y;
    float vz = acc.z * inv + bv.z;
    float vw = acc.w * inv + bv.w;

    float ss = vx * vx + vy * vy + vz * vz + vw * vw;
#pragma unroll
    for (int o = 8; o > 0; o >>= 1)
        ss += __shfl_xor_sync(0xffffffffu, ss, o);

    float scale = 1.f / fmaxf(sqrtf(ss), 1e-12f);
    if (half == 0) {
        reinterpret_cast<float4*>(out + (size_t)dst * D)[c] =
            make_float4(vx * scale, vy * scale, vz * scale, vw * scale);
    }
}

// ---------------------------------------------------------------------------
extern "C" void kernel_launch(void* const* d_in, const int* in_sizes, int n_in,
                              void* d_out, int out_size) {
    const float* embed = (const float*)d_in[0];
    const float* W     = (const float*)d_in[1];
    const float* att   = (const float*)d_in[2];
    const float* bias  = (const float*)d_in[3];
    const int*   edges = (const int*)d_in[7];
    float* out = (float*)d_out;

    k_gemm  <<<(N_NODES + 63) / 64, 256>>>(embed, W, att);   // 1563 blocks
    k_fill  <<<N_NODES / 8, 256>>>(edges);                   // 12500 blocks
    k_gather<<<N_NODES / 8, 256>>>(bias, out);               // 12500 blocks
}

// round 6
// speedup vs baseline: 2.1719x; 1.2576x over previous
#include <cuda_runtime.h>
#include <cuda_fp16.h>

#define N_NODES 100000
#define N_PAD   100032
#define K 32
#define D 64
#define CAP 96                   // per-dst bucket capacity (Poisson(32) tail ~1e-18)
#define NEG_SLOPE 0.2f

// Persistent scratch — fully rewritten every launch (replay-safe).
__device__ __align__(128) __half g_h16[(size_t)N_PAD * D];
__device__ float g_si[N_PAD];
__device__ float g_sj[N_PAD];
__device__ int   g_cnt[N_PAD];
__device__ __align__(128) int2  g_bkt[(size_t)N_NODES * CAP];

// ---------------------------------------------------------------------------
// Kernel 1 (tensor-core): h = embed @ W via mma.sync.m16n8k16 (fp16 in,
// fp32 accum). si = h.a_i, sj = h.a_j computed in fp32 from the c-fragments
// (each lane holds cols nt*8+kq..+1 of its rows; quad shfl reduction merges).
// sw2[kk][n] = fp16x2(W[2kk][n], W[2kk+1][n]); 72-word row stride keeps the
// b-fragment LDS access a lane permutation (conflict-free).
// 8 warps/block, 16 rows/warp -> 128 rows/block, grid 782.
// ---------------------------------------------------------------------------
__global__ void __launch_bounds__(256) k_gemm(const float* __restrict__ embed,
                                              const float* __restrict__ W,
                                              const float* __restrict__ att) {
    __shared__ unsigned sw2[32][72];
    __shared__ float s_att[128];

    int t = threadIdx.x;
    int base = blockIdx.x * 128;

    for (int idx = t; idx < 32 * 64; idx += 256) {
        int kk = idx >> 6, n = idx & 63;
        __half2 h2 = __floats2half2_rn(__ldg(&W[(2 * kk) * 64 + n]),
                                       __ldg(&W[(2 * kk + 1) * 64 + n]));
        sw2[kk][n] = *reinterpret_cast<unsigned*>(&h2);
    }
    if (t < 128) s_att[t] = __ldg(&att[t]);
    if (t < 128 && base + t < N_PAD) g_cnt[base + t] = 0;
    __syncthreads();

    int lane = t & 31, w = t >> 5;
    int r0 = base + w * 16 + (lane >> 2);
    int r1 = r0 + 8;
    int kq = (lane & 3) * 2;

    // A fragments for all 4 k-steps: a[ks] = {(r0,k),(r1,k),(r0,k+8),(r1,k+8)}
    unsigned a[4][4];
#pragma unroll
    for (int ks = 0; ks < 4; ks++) {
        int k = ks * 16 + kq;
        float2 f0 = (r0 < N_NODES) ? *reinterpret_cast<const float2*>(embed + (size_t)r0 * D + k)     : make_float2(0.f, 0.f);
        float2 f1 = (r1 < N_NODES) ? *reinterpret_cast<const float2*>(embed + (size_t)r1 * D + k)     : make_float2(0.f, 0.f);
        float2 f2 = (r0 < N_NODES) ? *reinterpret_cast<const float2*>(embed + (size_t)r0 * D + k + 8) : make_float2(0.f, 0.f);
        float2 f3 = (r1 < N_NODES) ? *reinterpret_cast<const float2*>(embed + (size_t)r1 * D + k + 8) : make_float2(0.f, 0.f);
        __half2 h;
        h = __floats2half2_rn(f0.x, f0.y); a[ks][0] = *reinterpret_cast<unsigned*>(&h);
        h = __floats2half2_rn(f1.x, f1.y); a[ks][1] = *reinterpret_cast<unsigned*>(&h);
        h = __floats2half2_rn(f2.x, f2.y); a[ks][2] = *reinterpret_cast<unsigned*>(&h);
        h = __floats2half2_rn(f3.x, f3.y); a[ks][3] = *reinterpret_cast<unsigned*>(&h);
    }

    int nb = lane >> 2;   // b-frag / c-frag column group
    float psi0 = 0.f, psj0 = 0.f, psi1 = 0.f, psj1 = 0.f;

#pragma unroll
    for (int nt = 0; nt < 8; nt++) {
        float c0 = 0.f, c1 = 0.f, c2 = 0.f, c3 = 0.f;
#pragma unroll
        for (int ks = 0; ks < 4; ks++) {
            unsigned b0 = sw2[ks * 8 + (lane & 3)][nt * 8 + nb];
            unsigned b1 = sw2[ks * 8 + (lane & 3) + 4][nt * 8 + nb];
            asm volatile(
                "mma.sync.aligned.m16n8k16.row.col.f32.f16.f16.f32 "
                "{%0,%1,%2,%3}, {%4,%5,%6,%7}, {%8,%9}, {%0,%1,%2,%3};"
                : "+f"(c0), "+f"(c1), "+f"(c2), "+f"(c3)
                : "r"(a[ks][0]), "r"(a[ks][1]), "r"(a[ks][2]), "r"(a[ks][3]),
                  "r"(b0), "r"(b1));
        }
        int col = nt * 8 + kq;

        // fp32 attention logit partials: row r0 holds (c0,c1), row r1 (c2,c3)
        float ai0 = s_att[col], ai1 = s_att[col + 1];
        float aj0 = s_att[64 + col], aj1 = s_att[64 + col + 1];
        psi0 += c0 * ai0 + c1 * ai1;
        psj0 += c0 * aj0 + c1 * aj1;
        psi1 += c2 * ai0 + c3 * ai1;
        psj1 += c2 * aj0 + c3 * aj1;

        __half2 h01 = __floats2half2_rn(c0, c1);
        __half2 h23 = __floats2half2_rn(c2, c3);
        if (r0 < N_NODES) *reinterpret_cast<__half2*>(g_h16 + (size_t)r0 * D + col) = h01;
        if (r1 < N_NODES) *reinterpret_cast<__half2*>(g_h16 + (size_t)r1 * D + col) = h23;
    }

    // Reduce across the quad (lanes 4g..4g+3 share rows r0/r1).
#pragma unroll
    for (int o = 1; o <= 2; o <<= 1) {
        psi0 += __shfl_xor_sync(0xffffffffu, psi0, o);
        psj0 += __shfl_xor_sync(0xffffffffu, psj0, o);
        psi1 += __shfl_xor_sync(0xffffffffu, psi1, o);
        psj1 += __shfl_xor_sync(0xffffffffu, psj1, o);
    }
    if ((lane & 3) == 0) {
        if (r0 < N_NODES) { g_si[r0] = psi0; g_sj[r0] = psj0; }
        if (r1 < N_NODES) { g_si[r1] = psi1; g_sj[r1] = psj1; }
    }
}

// ---------------------------------------------------------------------------
// Kernel 2: fill per-dst buckets with (src, e). Warp per src node.
// Softmax without max-shift (shift-invariant; alpha is O(1) for these inputs).
// ---------------------------------------------------------------------------
__global__ void __launch_bounds__(256) k_fill(const int* __restrict__ edges) {
    int lane = threadIdx.x & 31;
    int i = blockIdx.x * 8 + (threadIdx.x >> 5);

    int dst  = edges[(size_t)i * K + lane];   // coalesced
    float sj = g_sj[i];                       // broadcast
    float si = __ldg(&g_si[dst]);             // random (L1/L2 hit)
    float a  = si + sj;
    a = (a >= 0.f) ? a : NEG_SLOPE * a;

    if (dst != i) {                           // invalid (self) K-edges drop out
        float e = __expf(a);
        int pos = atomicAdd(&g_cnt[dst], 1);
        if (pos < CAP)
            g_bkt[(size_t)dst * CAP + pos] = make_int2(i, __float_as_int(e));
    }
}

// ---------------------------------------------------------------------------
// Kernel 3: gather + finalize. Warp per dst node; lane owns cols [4c..4c+3],
// c = lane&15, two edges per iteration (one per half-warp). Bucket + self-loop
// + zero pad staged in smem -> branch-free LDS.64 bcast -> LDG.64 -> FMA loop.
// out = normalize((sum h[src]*e) / denom + bias)
// ---------------------------------------------------------------------------
__global__ void __launch_bounds__(256) k_gather(const float* __restrict__ bias,
                                                float* __restrict__ out) {
    __shared__ int2 sb[8][CAP + 2];

    int lane = threadIdx.x & 31;
    int w    = threadIdx.x >> 5;
    int c    = lane & 15;
    int half = lane >> 4;
    int dst  = blockIdx.x * 8 + w;

    int deg = min(g_cnt[dst], CAP);
    const int2* bp = g_bkt + (size_t)dst * CAP;

    for (int j = lane; j < deg; j += 32)
        sb[w][j] = bp[j];

    float a = g_si[dst] + g_sj[dst];
    a = (a >= 0.f) ? a : NEG_SLOPE * a;
    float es = __expf(a);
    if (lane == 0) {
        sb[w][deg]     = make_int2(dst, __float_as_int(es));
        sb[w][deg + 1] = make_int2(0, 0);
    }
    __syncwarp();

    float4 acc = make_float4(0.f, 0.f, 0.f, 0.f);
    float  den = 0.f;

    int iters = (deg + 2) >> 1;
#pragma unroll 4
    for (int j = 0; j < iters; j++) {
        int2 ent = sb[w][2 * j + half];
        float e = __int_as_float(ent.y);
        uint2 u = reinterpret_cast<const uint2*>(g_h16 + (size_t)ent.x * D)[c];
        float2 fa = __half22float2(*reinterpret_cast<__half2*>(&u.x));
        float2 fb = __half22float2(*reinterpret_cast<__half2*>(&u.y));
        acc.x += fa.x * e; acc.y += fa.y * e;
        acc.z += fb.x * e; acc.w += fb.y * e;
        den += e;
    }

    acc.x += __shfl_xor_sync(0xffffffffu, acc.x, 16);
    acc.y += __shfl_xor_sync(0xffffffffu, acc.y, 16);
    acc.z += __shfl_xor_sync(0xffffffffu, acc.z, 16);
    acc.w += __shfl_xor_sync(0xffffffffu, acc.w, 16);
    den   += __shfl_xor_sync(0xffffffffu, den,   16);

    float4 bv = __ldg(reinterpret_cast<const float4*>(bias) + c);
    float inv = 1.f / (den + 1e-16f);
    float vx = acc.x * inv + bv.x;
    float vy = acc.y * inv + bv.y;
    float vz = acc.z * inv + bv.z;
    float vw = acc.w * inv + bv.w;

    float ss = vx * vx + vy * vy + vz * vz + vw * vw;
#pragma unroll
    for (int o = 8; o > 0; o >>= 1)
        ss += __shfl_xor_sync(0xffffffffu, ss, o);

    float scale = 1.f / fmaxf(sqrtf(ss), 1e-12f);
    if (half == 0) {
        reinterpret_cast<float4*>(out + (size_t)dst * D)[c] =
            make_float4(vx * scale, vy * scale, vz * scale, vw * scale);
    }
}

// ---------------------------------------------------------------------------
extern "C" void kernel_launch(void* const* d_in, const int* in_sizes, int n_in,
                              void* d_out, int out_size) {
    const float* embed = (const float*)d_in[0];
    const float* W     = (const float*)d_in[1];
    const float* att   = (const float*)d_in[2];
    const float* bias  = (const float*)d_in[3];
    const int*   edges = (const int*)d_in[7];
    float* out = (float*)d_out;

    k_gemm  <<<(N_NODES + 127) / 128, 256>>>(embed, W, att);  // 782 blocks
    k_fill  <<<N_NODES / 8, 256>>>(edges);                    // 12500 blocks
    k_gather<<<N_NODES / 8, 256>>>(bias, out);                // 12500 blocks
}